// round 17
// baseline (speedup 1.0000x reference)
#include <cuda_runtime.h>
#include <cuda_bf16.h>

// FWHT-4096 / sqrt(4096). R14 schedule with the middle H32 (bits 0..4 = lane
// bits) done via shfl.bfly instead of a shared-memory round trip: halves smem
// traffic (128 -> 64 ops/thread) and removes one barrier.
//
// Index i = Q*1024 + P*128 + D*32 + L, thread j = D*32 + L, regs r = Q*8 + P.
//   Stage A: H32 over r=(Q,P)=i[7:12]  in regs          (160 FADD)
//   Stage B: H32 over L=i[0:5]         via shfl.bfly    (160 SHFL + 160 FFMA)
//   Stage C: H4  over D=i[5:7]         via one smem transpose + reg butterflies
// Hadamard bit-stages commute -> equals the reference 12-stage FWHT.
//
// Smem phys = r*132 + j  (132 == 4 mod 32):
//   write (lanes j):              banks = j + 4r          -> conflict-free
//   read  s[r*132 + D*32 + L]:    banks = L + const/instr -> conflict-free

#define FWHT_N 4096
#define ROW_THREADS 128
#define S_R 132
#define S_ROW (32 * S_R)   // 4224 floats (16.9 KB)

__device__ __forceinline__ void h32(float v[32]) {
#pragma unroll
    for (int h = 1; h < 32; h <<= 1) {
#pragma unroll
        for (int i = 0; i < 32; i++) {
            if (!(i & h)) {
                float a = v[i], b = v[i | h];
                v[i]     = a + b;
                v[i | h] = a - b;
            }
        }
    }
}

__global__ void __launch_bounds__(ROW_THREADS, 8)
fwht4096_kernel(const float* __restrict__ x, float* __restrict__ out) {
    __shared__ float s[S_ROW];

    const int j = threadIdx.x;
    const int L = j & 31;
    const size_t row = blockIdx.x;

    const float* __restrict__ xr = x + row * FWHT_N;
    float* __restrict__ orow     = out + row * FWHT_N;

    float v[32];

    // ---- Load: lanes = L -> one 128B line per warp-instr. ----
#pragma unroll
    for (int r = 0; r < 32; r++) v[r] = __ldcs(xr + r * 128 + j);

    // ---- Stage A: H32 over regs (index bits 7..11). ----
    h32(v);

    // ---- Stage B: H32 over lanes (index bits 0..4) via butterfly shuffles.
    //      low:  a+b = v + partner ; high: a-b = partner - v  ->  fmaf(sgn,v,o)
#pragma unroll
    for (int h = 1; h < 32; h <<= 1) {
        const float sgn = (L & h) ? -1.0f : 1.0f;
#pragma unroll
        for (int r = 0; r < 32; r++) {
            float o = __shfl_xor_sync(0xffffffffu, v[r], h);
            v[r] = fmaf(sgn, v[r], o);
        }
    }

    // ---- Stage C: H4 over D (index bits 5..6) via one transpose. ----
    {
        float* w = s + j;
#pragma unroll
        for (int r = 0; r < 32; r++) w[r * S_R] = v[r];   // banks j+4r -> CF
    }
    __syncthreads();
    {
        const int G = j >> 5;               // warp id -> Q
        const float* b = s + (G * 8) * S_R + L;
#pragma unroll
        for (int k = 0; k < 32; k++) {      // k = P*4 + D
            const int P = k >> 2, D = k & 3;
            v[k] = b[P * S_R + D * 32];     // banks = L + const -> CF
        }
        // H4 over D = reg bits 0..1
#pragma unroll
        for (int h = 1; h < 4; h <<= 1) {
#pragma unroll
            for (int i = 0; i < 32; i++) {
                if (!(i & h)) {
                    float a = v[i], c = v[i | h];
                    v[i]     = a + c;
                    v[i | h] = a - c;
                }
            }
        }
        const float scale = 1.0f / 64.0f;   // 1/sqrt(4096)
        float* o = orow + G * 1024 + L;
        // store addr = G*1024 + P*128 + D*32 + L; lanes = L -> fully coalesced
#pragma unroll
        for (int k = 0; k < 32; k++) {
            const int P = k >> 2, D = k & 3;
            __stcs(o + P * 128 + D * 32, v[k] * scale);
        }
    }
}

extern "C" void kernel_launch(void* const* d_in, const int* in_sizes, int n_in,
                              void* d_out, int out_size) {
    const float* x = (const float*)d_in[0];
    float* out     = (float*)d_out;
    const int nrows = in_sizes[0] / FWHT_N;   // 16384
    fwht4096_kernel<<<nrows, ROW_THREADS>>>(x, out);
}